// round 3
// baseline (speedup 1.0000x reference)
#include <cuda_runtime.h>
#include <math.h>

// Problem constants (fixed shapes)
#define BN 2048
#define ZD 512
#define HD 384
#define TN 32
#define G4 (4*HD)              // 1536
#define OUT_STRIDE (TN*ZD)     // 16384  (row stride between consecutive batch rows in `out`)
#define E_STRIDE ((TN-1)*ZD)   // 15872
#define HC_STRIDE (2*HD)       // 768
#define SEQ ((TN-1)*BN)        // 63488

// Scratch (allocation-free: __device__ globals)
__device__ float g_gates[(size_t)BN*G4];          // 12.6 MB
__device__ float g_h[(size_t)BN*HD];
__device__ float g_c[(size_t)BN*HD];
__device__ float g_hc[(size_t)SEQ*HC_STRIDE];     // 195 MB
__device__ float g_mid[(size_t)SEQ*ZD];           // 130 MB

__device__ __forceinline__ float sigf(float x) { return 1.0f / (1.0f + __expf(-x)); }

// ---------------------------------------------------------------------------
// Generic 128x128x8 SGEMM, NT layout (C[m,n] = sum_k A[m,k] * W[n,k]).
// Optional second (A2, B2) pair accumulated into the same C (for gates GEMM).
// EPI: 0 = raw store, 1 = relu(acc + bias), 2 = acc + bias
// ---------------------------------------------------------------------------
template<int EPI>
__global__ __launch_bounds__(256, 2) void sgemm128(
    const float* __restrict__ A1, int lda1, int K1,
    const float* __restrict__ A2, int lda2, int K2,
    const float* __restrict__ B1, const float* __restrict__ B2,
    const float* __restrict__ bias,
    float* __restrict__ C, int ldc)
{
    __shared__ float As[8][128];
    __shared__ float Bs[8][128];
    const int tid = threadIdx.x;
    const int bm = blockIdx.y * 128;
    const int bn = blockIdx.x * 128;
    const int lr = tid >> 1;           // 0..127
    const int lc = (tid & 1) << 2;     // 0 or 4
    const int ty = tid >> 4;           // 0..15
    const int tx = tid & 15;           // 0..15

    float acc[8][8];
#pragma unroll
    for (int i = 0; i < 8; i++)
#pragma unroll
        for (int j = 0; j < 8; j++) acc[i][j] = 0.0f;

#pragma unroll 1
    for (int part = 0; part < 2; ++part) {
        const float* A  = part ? A2 : A1;
        const float* Bw = part ? B2 : B1;
        const int lda   = part ? lda2 : lda1;
        const int K     = part ? K2 : K1;
        if (A == nullptr || K == 0) continue;
        const float* Arow = A  + (size_t)(bm + lr) * lda + lc;
        const float* Brow = Bw + (size_t)(bn + lr) * K + lc;
#pragma unroll 1
        for (int k0 = 0; k0 < K; k0 += 8) {
            float4 av = *(const float4*)(Arow + k0);
            float4 bv = *(const float4*)(Brow + k0);
            __syncthreads();
            As[lc+0][lr] = av.x; As[lc+1][lr] = av.y; As[lc+2][lr] = av.z; As[lc+3][lr] = av.w;
            Bs[lc+0][lr] = bv.x; Bs[lc+1][lr] = bv.y; Bs[lc+2][lr] = bv.z; Bs[lc+3][lr] = bv.w;
            __syncthreads();
#pragma unroll
            for (int kk = 0; kk < 8; kk++) {
                float af[8], bf[8];
                *(float4*)(af    ) = *(const float4*)(&As[kk][ty * 8]);
                *(float4*)(af + 4) = *(const float4*)(&As[kk][ty * 8 + 4]);
                *(float4*)(bf    ) = *(const float4*)(&Bs[kk][tx * 8]);
                *(float4*)(bf + 4) = *(const float4*)(&Bs[kk][tx * 8 + 4]);
#pragma unroll
                for (int i = 0; i < 8; i++)
#pragma unroll
                    for (int j = 0; j < 8; j++)
                        acc[i][j] = fmaf(af[i], bf[j], acc[i][j]);
            }
        }
    }

#pragma unroll
    for (int i = 0; i < 8; i++) {
        const int m = bm + ty * 8 + i;
#pragma unroll
        for (int j = 0; j < 8; j++) {
            const int n = bn + tx * 8 + j;
            float v = acc[i][j];
            if (EPI == 1) v = fmaxf(v + bias[n], 0.0f);
            if (EPI == 2) v = v + bias[n];
            C[(size_t)m * ldc + n] = v;
        }
    }
}

// ---------------------------------------------------------------------------
// mul GEMM: C = tanh(h2 @ w + b); out_new = out_prev + 0.2*C
// 64x64x16 tiles, NN layout (w is [K=384, N=512] row-major).
// Fuses residual update + `out` write + `e` write.
// ---------------------------------------------------------------------------
__global__ __launch_bounds__(256) void gemm_mul(
    const float* __restrict__ H2,      // [2048, 384]
    const float* __restrict__ W,       // [384, 512]
    const float* __restrict__ bias,    // [512]
    const float* __restrict__ outPrev, // stride OUT_STRIDE
    float* __restrict__ outNew,        // stride OUT_STRIDE
    float* __restrict__ ePtr)          // stride E_STRIDE, may be null
{
    __shared__ float As[16][64];
    __shared__ float Bs[16][64];
    const int tid = threadIdx.x;
    const int bm = blockIdx.y * 64;
    const int bn = blockIdx.x * 64;
    const int ar   = tid >> 2;          // 0..63
    const int akc  = (tid & 3) << 2;    // 0,4,8,12
    const int bkr  = tid >> 4;          // 0..15
    const int bcol = (tid & 15) << 2;   // 0..60
    const int ty = tid >> 4;
    const int tx = tid & 15;

    float acc[4][4];
#pragma unroll
    for (int i = 0; i < 4; i++)
#pragma unroll
        for (int j = 0; j < 4; j++) acc[i][j] = 0.0f;

#pragma unroll 1
    for (int k0 = 0; k0 < HD; k0 += 16) {
        float4 av = *(const float4*)(H2 + (size_t)(bm + ar) * HD + k0 + akc);
        float4 bv = *(const float4*)(W + (size_t)(k0 + bkr) * ZD + bn + bcol);
        __syncthreads();
        As[akc+0][ar] = av.x; As[akc+1][ar] = av.y; As[akc+2][ar] = av.z; As[akc+3][ar] = av.w;
        *(float4*)(&Bs[bkr][bcol]) = bv;
        __syncthreads();
#pragma unroll
        for (int kk = 0; kk < 16; kk++) {
            float af[4], bf[4];
            *(float4*)af = *(const float4*)(&As[kk][ty * 4]);
            *(float4*)bf = *(const float4*)(&Bs[kk][tx * 4]);
#pragma unroll
            for (int i = 0; i < 4; i++)
#pragma unroll
                for (int j = 0; j < 4; j++)
                    acc[i][j] = fmaf(af[i], bf[j], acc[i][j]);
        }
    }

#pragma unroll
    for (int i = 0; i < 4; i++) {
        const int m = bm + ty * 4 + i;
#pragma unroll
        for (int j = 0; j < 4; j++) {
            const int n = bn + tx * 4 + j;
            float v = acc[i][j] + bias[n];
            float o = outPrev[(size_t)m * OUT_STRIDE + n] + 0.2f * tanhf(v);
            outNew[(size_t)m * OUT_STRIDE + n] = o;
            if (ePtr) ePtr[(size_t)m * E_STRIDE + n] = o;
        }
    }
}

// ---------------------------------------------------------------------------
// LSTM pointwise: gates [B,4H] (i,f,g,o) -> h,c update; optional scatter into hc
// ---------------------------------------------------------------------------
__global__ void lstm_pointwise(
    const float* __restrict__ gates,
    const float* __restrict__ bih, const float* __restrict__ bhh,
    float* __restrict__ h, float* __restrict__ c,
    int useC,
    float* __restrict__ hcRow, int hcStride)
{
    int idx = blockIdx.x * blockDim.x + threadIdx.x;
    if (idx >= BN * HD) return;
    int b = idx / HD, j = idx - b * HD;
    const float* g = gates + (size_t)b * G4;
    float gi = g[j         ] + bih[j         ] + bhh[j         ];
    float gf = g[j +   HD  ] + bih[j +   HD  ] + bhh[j +   HD  ];
    float gg = g[j + 2*HD  ] + bih[j + 2*HD  ] + bhh[j + 2*HD  ];
    float go = g[j + 3*HD  ] + bih[j + 3*HD  ] + bhh[j + 3*HD  ];
    float cn = sigf(gi) * tanhf(gg);
    if (useC) cn += sigf(gf) * c[idx];
    float hn = sigf(go) * tanhf(cn);
    c[idx] = cn;
    h[idx] = hn;
    if (hcRow) {
        float* r = hcRow + (size_t)b * hcStride;
        r[j] = hn;
        r[HD + j] = cn;
    }
}

// out[b*32+0] = z[b]; e[b*31+0] = z[b]
__global__ void init_out(const float* __restrict__ z,
                         float* __restrict__ out, float* __restrict__ e)
{
    int idx = blockIdx.x * blockDim.x + threadIdx.x;
    if (idx >= BN * ZD) return;
    int b = idx >> 9, n = idx & 511;
    float v = z[idx];
    out[(size_t)b * OUT_STRIDE + n] = v;
    e[(size_t)b * E_STRIDE + n] = v;
}

extern "C" void kernel_launch(void* const* d_in, const int* in_sizes, int n_in,
                              void* d_out, int out_size)
{
    (void)in_sizes; (void)n_in; (void)out_size;
    const float* z       = (const float*)d_in[0];
    const float* Wih_enc = (const float*)d_in[1];
    const float* Whh_enc = (const float*)d_in[2];
    const float* bih_enc = (const float*)d_in[3];
    const float* bhh_enc = (const float*)d_in[4];
    const float* Wih     = (const float*)d_in[5];
    const float* Whh     = (const float*)d_in[6];
    const float* bih     = (const float*)d_in[7];
    const float* bhh     = (const float*)d_in[8];
    const float* w       = (const float*)d_in[9];
    const float* b       = (const float*)d_in[10];
    const float* fc1_w   = (const float*)d_in[11];
    const float* fc1_b   = (const float*)d_in[12];
    const float* fc2_w   = (const float*)d_in[13];
    const float* fc2_b   = (const float*)d_in[14];
    (void)Whh_enc; // h0 = 0 so the enc Whh term vanishes

    float* out  = (float*)d_out;
    float* e    = out + (size_t)BN * TN * ZD;
    float* erec = e + (size_t)SEQ * ZD;

    float *gates, *h, *c, *hc, *mid;
    cudaGetSymbolAddress((void**)&gates, g_gates);
    cudaGetSymbolAddress((void**)&h,     g_h);
    cudaGetSymbolAddress((void**)&c,     g_c);
    cudaGetSymbolAddress((void**)&hc,    g_hc);
    cudaGetSymbolAddress((void**)&mid,   g_mid);

    const dim3 blk(256);

    // t = 0: out/e row 0 = z
    init_out<<<(BN * ZD) / 256, blk>>>(z, out, e);

    // Encoder cell (h=c=0): gates = z @ Wih_enc^T
    sgemm128<0><<<dim3(G4 / 128, BN / 128), blk>>>(
        z, ZD, ZD, nullptr, 0, 0, Wih_enc, nullptr, nullptr, gates, G4);
    lstm_pointwise<<<(BN * HD) / 256, blk>>>(
        gates, bih_enc, bhh_enc, h, c, 0, nullptr, 0);

    // 31 recurrent steps
    for (int k = 0; k < TN - 1; ++k) {
        // gates = out_prev @ Wih^T + h @ Whh^T (out_prev = out rows at time k)
        sgemm128<0><<<dim3(G4 / 128, BN / 128), blk>>>(
            out + (size_t)k * ZD, OUT_STRIDE, ZD,
            h, HD, HD,
            Wih, Whh, nullptr, gates, G4);
        lstm_pointwise<<<(BN * HD) / 256, blk>>>(
            gates, bih, bhh, h, c, 1,
            hc + (size_t)k * HC_STRIDE, (TN - 1) * HC_STRIDE);
        // out_{k+1} = out_k + 0.2*tanh(h2 @ w + b); also writes e row k+1 (k+1 <= 30)
        gemm_mul<<<dim3(ZD / 64, BN / 64), blk>>>(
            h, w, b,
            out + (size_t)k * ZD,
            out + (size_t)(k + 1) * ZD,
            (k + 1 <= TN - 2) ? (e + (size_t)(k + 1) * ZD) : nullptr);
    }

    // e_rec = relu(hc @ fc1_w^T + fc1_b) @ fc2_w^T + fc2_b
    sgemm128<1><<<dim3(ZD / 128, SEQ / 128), blk>>>(
        hc, HC_STRIDE, HC_STRIDE, nullptr, 0, 0, fc1_w, nullptr, fc1_b, mid, ZD);
    sgemm128<2><<<dim3(ZD / 128, SEQ / 128), blk>>>(
        mid, ZD, ZD, nullptr, 0, 0, fc2_w, nullptr, fc2_b, erec, ZD);
}

// round 7
// speedup vs baseline: 2.3794x; 2.3794x over previous
#include <cuda_runtime.h>
#include <math.h>
#include <stdint.h>

// Problem constants (fixed shapes)
#define BN 2048
#define ZD 512
#define HD 384
#define TN 32
#define G4 (4*HD)              // 1536
#define OUT_STRIDE (TN*ZD)     // 16384
#define E_STRIDE ((TN-1)*ZD)   // 15872
#define HC_STRIDE (2*HD)       // 768
#define SEQ ((TN-1)*BN)        // 63488

#define LDS 36                 // smem row stride in floats (32 + 4 pad, conflict-free frags)

// Scratch (allocation-free: __device__ globals)
__device__ float g_gates[(size_t)BN*G4];
__device__ float g_h[(size_t)BN*HD];
__device__ float g_c[(size_t)BN*HD];
__device__ float g_hc[(size_t)SEQ*HC_STRIDE];
__device__ float g_mid[(size_t)SEQ*ZD];
__device__ float g_wT[(size_t)ZD*HD];     // w transposed to [Z, H] K-major

__device__ __forceinline__ float sigf(float x) { return 1.0f / (1.0f + __expf(-x)); }

__device__ __forceinline__ uint32_t f2tf(float x) {
    uint32_t r;
    asm("cvt.rna.tf32.f32 %0, %1;" : "=r"(r) : "f"(x));
    return r;
}

__device__ __forceinline__ void mma_tf32(
    float* c, uint32_t a0, uint32_t a1, uint32_t a2, uint32_t a3,
    uint32_t b0, uint32_t b1)
{
    asm volatile(
        "mma.sync.aligned.m16n8k8.row.col.f32.tf32.tf32.f32 "
        "{%0,%1,%2,%3}, {%4,%5,%6,%7}, {%8,%9}, {%0,%1,%2,%3};"
        : "+f"(c[0]), "+f"(c[1]), "+f"(c[2]), "+f"(c[3])
        : "r"(a0), "r"(a1), "r"(a2), "r"(a3), "r"(b0), "r"(b1));
}

// Load a [ROWS x 32 floats] K-major tile gmem -> tf32 smem (stride LDS).
// 256 threads. ROWS = 128 (2 thr/row) or 64 (4 thr/row).
template<int ROWS>
__device__ __forceinline__ void load_tile(
    const float* __restrict__ G, int row0, int ld, int k0,
    uint32_t* __restrict__ dst, int tid)
{
    constexpr int TPR  = 256 / ROWS;   // threads per row
    constexpr int F4PT = 8 / TPR;      // float4s per thread
    const int row = tid / TPR;
    const int f0  = (tid % TPR) * F4PT;
    const float4* src = (const float4*)(G + (size_t)(row0 + row) * ld + k0);
    uint32_t* d = dst + row * LDS;
#pragma unroll
    for (int i = 0; i < F4PT; i++) {
        float4 v = src[f0 + i];
        uint4 t;
        t.x = f2tf(v.x); t.y = f2tf(v.y); t.z = f2tf(v.z); t.w = f2tf(v.w);
        *(uint4*)(d + (f0 + i) * 4) = t;
    }
}

// ---------------------------------------------------------------------------
// tf32 mma.sync GEMM, NT layout (C[m,n] = sum_k A[m,k] * W[n,k]).
// Block: 256 thr = 8 warps (4m x 2n). Warp tile 32 x (NF*8).
// Block tile: 128 x (NF*16).  NF=8 -> 128x128, NF=4 -> 128x64.
// K chunked by 32. Dual-A (A1/B1 over K1 then A2/B2 over K2) into same acc.
// EPI: 0 raw; 1 relu(acc+bias); 2 acc+bias;
//      3 out = outPrev + 0.2*tanh(acc+bias), mirrored to ePtr (e rows)
// ---------------------------------------------------------------------------
template<int EPI, int NF>
__global__ __launch_bounds__(256, 2) void tf32_gemm(
    const float* __restrict__ A1, int lda1, int K1,
    const float* __restrict__ A2, int lda2, int K2,
    const float* __restrict__ B1, int ldb1,
    const float* __restrict__ B2, int ldb2,
    const float* __restrict__ bias,
    float* __restrict__ C, int ldc,
    const float* __restrict__ outPrev, float* __restrict__ ePtr)
{
    constexpr int BROWS = NF * 16;           // B tile rows (= block N)
    __shared__ uint32_t As[128 * LDS];
    __shared__ uint32_t Bs[BROWS * LDS];

    const int tid  = threadIdx.x;
    const int wid  = tid >> 5, lane = tid & 31;
    const int grp  = lane >> 2, tig = lane & 3;
    const int wm   = (wid >> 1) * 32;        // warp m offset in tile
    const int wn   = (wid & 1) * (NF * 8);   // warp n offset in tile
    const int bm   = blockIdx.y * 128;
    const int bn   = blockIdx.x * BROWS;

    float acc[2][NF][4];
#pragma unroll
    for (int mi = 0; mi < 2; mi++)
#pragma unroll
        for (int ni = 0; ni < NF; ni++)
#pragma unroll
            for (int j = 0; j < 4; j++) acc[mi][ni][j] = 0.0f;

    const int nch1 = K1 >> 5;
    const int nch  = nch1 + (K2 >> 5);

#pragma unroll 1
    for (int c = 0; c < nch; ++c) {
        const float* Ap; const float* Bp; int la, lb, k0;
        if (c < nch1) { Ap = A1; Bp = B1; la = lda1; lb = ldb1; k0 = c << 5; }
        else          { Ap = A2; Bp = B2; la = lda2; lb = ldb2; k0 = (c - nch1) << 5; }
        __syncthreads();
        load_tile<128>(Ap, bm, la, k0, As, tid);
        load_tile<BROWS>(Bp, bn, lb, k0, Bs, tid);
        __syncthreads();
#pragma unroll
        for (int s = 0; s < 4; s++) {
            const int k = s * 8;
            uint32_t a[2][4], bf[NF][2];
#pragma unroll
            for (int mi = 0; mi < 2; mi++) {
                const uint32_t* p0 = As + (wm + mi * 16 + grp) * LDS + k + tig;
                const uint32_t* p1 = p0 + 8 * LDS;
                a[mi][0] = p0[0]; a[mi][2] = p0[4];
                a[mi][1] = p1[0]; a[mi][3] = p1[4];
            }
#pragma unroll
            for (int ni = 0; ni < NF; ni++) {
                const uint32_t* pb = Bs + (wn + ni * 8 + grp) * LDS + k + tig;
                bf[ni][0] = pb[0]; bf[ni][1] = pb[4];
            }
#pragma unroll
            for (int mi = 0; mi < 2; mi++)
#pragma unroll
                for (int ni = 0; ni < NF; ni++)
                    mma_tf32(acc[mi][ni], a[mi][0], a[mi][1], a[mi][2], a[mi][3],
                             bf[ni][0], bf[ni][1]);
        }
    }

    // Epilogue. C frag mapping (m16n8): c0,c1 at (grp, 2*tig..+1); c2,c3 at (grp+8, same).
    auto emit = [&](int row, int col, float v0, float v1) {
        if (EPI == 0) {
            float2 v = make_float2(v0, v1);
            *(float2*)&C[(size_t)row * ldc + col] = v;
        } else if (EPI == 1 || EPI == 2) {
            v0 += bias[col]; v1 += bias[col + 1];
            if (EPI == 1) { v0 = fmaxf(v0, 0.f); v1 = fmaxf(v1, 0.f); }
            float2 v = make_float2(v0, v1);
            *(float2*)&C[(size_t)row * ldc + col] = v;
        } else {
            float2 op = *(const float2*)&outPrev[(size_t)row * OUT_STRIDE + col];
            float2 o;
            o.x = op.x + 0.2f * tanhf(v0 + bias[col]);
            o.y = op.y + 0.2f * tanhf(v1 + bias[col + 1]);
            *(float2*)&C[(size_t)row * ldc + col] = o;
            if (ePtr) *(float2*)&ePtr[(size_t)row * E_STRIDE + col] = o;
        }
    };

#pragma unroll
    for (int mi = 0; mi < 2; mi++) {
        const int r0 = bm + wm + mi * 16 + grp;
#pragma unroll
        for (int ni = 0; ni < NF; ni++) {
            const int col = bn + wn + ni * 8 + 2 * tig;
            emit(r0,     col, acc[mi][ni][0], acc[mi][ni][1]);
            emit(r0 + 8, col, acc[mi][ni][2], acc[mi][ni][3]);
        }
    }
}

// ---------------------------------------------------------------------------
// LSTM pointwise
// ---------------------------------------------------------------------------
__global__ void lstm_pointwise(
    const float* __restrict__ gates,
    const float* __restrict__ bih, const float* __restrict__ bhh,
    float* __restrict__ h, float* __restrict__ c,
    int useC,
    float* __restrict__ hcRow, int hcStride)
{
    int idx = blockIdx.x * blockDim.x + threadIdx.x;
    if (idx >= BN * HD) return;
    int b = idx / HD, j = idx - b * HD;
    const float* g = gates + (size_t)b * G4;
    float gi = g[j        ] + bih[j        ] + bhh[j        ];
    float gf = g[j +   HD ] + bih[j +   HD ] + bhh[j +   HD ];
    float gg = g[j + 2*HD ] + bih[j + 2*HD ] + bhh[j + 2*HD ];
    float go = g[j + 3*HD ] + bih[j + 3*HD ] + bhh[j + 3*HD ];
    float cn = sigf(gi) * tanhf(gg);
    if (useC) cn += sigf(gf) * c[idx];
    float hn = sigf(go) * tanhf(cn);
    c[idx] = cn;
    h[idx] = hn;
    if (hcRow) {
        float* r = hcRow + (size_t)b * hcStride;
        r[j] = hn;
        r[HD + j] = cn;
    }
}

__global__ void init_out(const float* __restrict__ z,
                         float* __restrict__ out, float* __restrict__ e)
{
    int idx = blockIdx.x * blockDim.x + threadIdx.x;
    if (idx >= BN * ZD) return;
    int b = idx >> 9, n = idx & 511;
    float v = z[idx];
    out[(size_t)b * OUT_STRIDE + n] = v;
    e[(size_t)b * E_STRIDE + n] = v;
}

// wT[n, k] = w[k, n]   (w: [H=384, Z=512] row-major -> wT: [512, 384] K-major)
__global__ void transpose_w(const float* __restrict__ w, float* __restrict__ wT)
{
    int idx = blockIdx.x * blockDim.x + threadIdx.x;
    if (idx >= ZD * HD) return;
    int n = idx / HD, k = idx - n * HD;
    wT[idx] = w[(size_t)k * ZD + n];
}

extern "C" void kernel_launch(void* const* d_in, const int* in_sizes, int n_in,
                              void* d_out, int out_size)
{
    (void)in_sizes; (void)n_in; (void)out_size;
    const float* z       = (const float*)d_in[0];
    const float* Wih_enc = (const float*)d_in[1];
    const float* Whh_enc = (const float*)d_in[2];
    const float* bih_enc = (const float*)d_in[3];
    const float* bhh_enc = (const float*)d_in[4];
    const float* Wih     = (const float*)d_in[5];
    const float* Whh     = (const float*)d_in[6];
    const float* bih     = (const float*)d_in[7];
    const float* bhh     = (const float*)d_in[8];
    const float* w       = (const float*)d_in[9];
    const float* b       = (const float*)d_in[10];
    const float* fc1_w   = (const float*)d_in[11];
    const float* fc1_b   = (const float*)d_in[12];
    const float* fc2_w   = (const float*)d_in[13];
    const float* fc2_b   = (const float*)d_in[14];
    (void)Whh_enc; // h0 = 0 so the enc Whh term vanishes

    float* out  = (float*)d_out;
    float* e    = out + (size_t)BN * TN * ZD;
    float* erec = e + (size_t)SEQ * ZD;

    float *gates, *h, *c, *hc, *mid, *wT;
    cudaGetSymbolAddress((void**)&gates, g_gates);
    cudaGetSymbolAddress((void**)&h,     g_h);
    cudaGetSymbolAddress((void**)&c,     g_c);
    cudaGetSymbolAddress((void**)&hc,    g_hc);
    cudaGetSymbolAddress((void**)&mid,   g_mid);
    cudaGetSymbolAddress((void**)&wT,    g_wT);

    const dim3 blk(256);

    init_out<<<(BN * ZD) / 256, 256>>>(z, out, e);
    transpose_w<<<(ZD * HD) / 256, 256>>>(w, wT);

    // Encoder: gates = z @ Wih_enc^T   (h0 = c0 = 0)
    tf32_gemm<0, 8><<<dim3(G4 / 128, BN / 128), blk>>>(
        z, ZD, ZD, nullptr, 0, 0, Wih_enc, ZD, nullptr, 0,
        nullptr, gates, G4, nullptr, nullptr);
    lstm_pointwise<<<(BN * HD) / 256, 256>>>(
        gates, bih_enc, bhh_enc, h, c, 0, nullptr, 0);

    // 31 recurrent steps
    for (int k = 0; k < TN - 1; ++k) {
        // gates = out_prev @ Wih^T + h @ Whh^T
        tf32_gemm<0, 8><<<dim3(G4 / 128, BN / 128), blk>>>(
            out + (size_t)k * ZD, OUT_STRIDE, ZD,
            h, HD, HD,
            Wih, ZD, Whh, HD,
            nullptr, gates, G4, nullptr, nullptr);
        lstm_pointwise<<<(BN * HD) / 256, 256>>>(
            gates, bih, bhh, h, c, 1,
            hc + (size_t)k * HC_STRIDE, (TN - 1) * HC_STRIDE);
        // out_{k+1} = out_k + 0.2*tanh(h2 @ wT^T + b); mirrors into e row k+1
        // NF=4 (128x64 tile) -> 128 CTAs for better SM coverage on N=512
        tf32_gemm<3, 4><<<dim3(ZD / 64, BN / 128), blk>>>(
            h, HD, HD, nullptr, 0, 0, wT, HD, nullptr, 0,
            b, out + (size_t)(k + 1) * ZD, OUT_STRIDE,
            out + (size_t)k * ZD,
            (k + 1 <= TN - 2) ? (e + (size_t)(k + 1) * ZD) : nullptr);
    }

    // e_rec = relu(hc @ fc1_w^T + fc1_b) @ fc2_w^T + fc2_b
    tf32_gemm<1, 8><<<dim3(ZD / 128, SEQ / 128), blk>>>(
        hc, HC_STRIDE, HC_STRIDE, nullptr, 0, 0, fc1_w, HC_STRIDE, nullptr, 0,
        fc1_b, mid, ZD, nullptr, nullptr);
    tf32_gemm<2, 8><<<dim3(ZD / 128, SEQ / 128), blk>>>(
        mid, ZD, ZD, nullptr, 0, 0, fc2_w, ZD, nullptr, 0,
        fc2_b, erec, ZD, nullptr, nullptr);
}

// round 8
// speedup vs baseline: 3.0269x; 1.2721x over previous
#include <cuda_runtime.h>
#include <math.h>
#include <stdint.h>

// Problem constants (fixed shapes)
#define BN 2048
#define ZD 512
#define HD 384
#define TN 32
#define G4 (4*HD)              // 1536
#define OUT_STRIDE (TN*ZD)     // 16384
#define E_STRIDE ((TN-1)*ZD)   // 15872
#define HC_STRIDE (2*HD)       // 768
#define SEQ ((TN-1)*BN)        // 63488

#define LDS 36                 // smem row stride in words (32 + 4 pad; rows hit distinct bank groups)

// Scratch (allocation-free: __device__ globals)
__device__ float g_gates[(size_t)BN*G4];
__device__ float g_h[(size_t)BN*HD];       // tf32-rounded h
__device__ float g_c[(size_t)BN*HD];       // exact c
__device__ float g_hc[(size_t)SEQ*HC_STRIDE];   // tf32-rounded (h,c)
__device__ float g_mid[(size_t)SEQ*ZD];         // tf32-rounded fc1 output
__device__ float g_outTf[(size_t)BN*ZD];        // tf32-rounded out row (current step)
// tf32-rounded weights
__device__ float g_WihEnc_t[(size_t)G4*ZD];
__device__ float g_Wih_t[(size_t)G4*ZD];
__device__ float g_Whh_t[(size_t)G4*HD];
__device__ float g_fc1_t[(size_t)ZD*HC_STRIDE];
__device__ float g_fc2_t[(size_t)ZD*ZD];
__device__ float g_wT[(size_t)ZD*HD];           // rounded transpose of w

__device__ __forceinline__ float sigf(float x) { return 1.0f / (1.0f + __expf(-x)); }

__device__ __forceinline__ uint32_t f2tf(float x) {
    uint32_t r;
    asm("cvt.rna.tf32.f32 %0, %1;" : "=r"(r) : "f"(x));
    return r;
}
__device__ __forceinline__ float rtf(float x) { return __uint_as_float(f2tf(x)); }

__device__ __forceinline__ uint32_t smem_u32(const void* p) {
    uint32_t a;
    asm("{ .reg .u64 t; cvta.to.shared.u64 t, %1; cvt.u32.u64 %0, t; }" : "=r"(a) : "l"(p));
    return a;
}

__device__ __forceinline__ void mma_tf32(
    float* c, uint32_t a0, uint32_t a1, uint32_t a2, uint32_t a3,
    uint32_t b0, uint32_t b1)
{
    asm volatile(
        "mma.sync.aligned.m16n8k8.row.col.f32.tf32.tf32.f32 "
        "{%0,%1,%2,%3}, {%4,%5,%6,%7}, {%8,%9}, {%0,%1,%2,%3};"
        : "+f"(c[0]), "+f"(c[1]), "+f"(c[2]), "+f"(c[3])
        : "r"(a0), "r"(a1), "r"(a2), "r"(a3), "r"(b0), "r"(b1));
}

__device__ __forceinline__ void ldm4(uint32_t* r, uint32_t addr) {
    asm volatile("ldmatrix.sync.aligned.m8n8.x4.shared.b16 {%0,%1,%2,%3}, [%4];"
        : "=r"(r[0]), "=r"(r[1]), "=r"(r[2]), "=r"(r[3]) : "r"(addr));
}

__device__ __forceinline__ void cpa16(uint32_t dst, const void* src) {
    asm volatile("cp.async.ca.shared.global [%0], [%1], 16;" :: "r"(dst), "l"(src));
}

// Issue cp.async for a [ROWS x 32 floats] K-major tile into smem (row stride LDS words).
template<int ROWS>
__device__ __forceinline__ void issue_tile(
    const float* __restrict__ G, int row0, int ld, int k0, uint32_t smemBase, int tid)
{
    constexpr int TPR = 256 / ROWS;    // threads per row
    constexpr int SPT = 8 / TPR;       // 16B segments per thread
    const int row = tid / TPR;
    const int s0  = (tid % TPR) * SPT;
    const float* src = G + (size_t)(row0 + row) * ld + k0 + s0 * 4;
    uint32_t d = smemBase + (uint32_t)(row * LDS + s0 * 4) * 4u;
#pragma unroll
    for (int i = 0; i < SPT; i++) cpa16(d + i * 16, src + i * 4);
}

// ---------------------------------------------------------------------------
// tf32 mma.sync GEMM, NT layout, cp.async double-buffered, ldmatrix frags.
// All inputs PRE-ROUNDED to tf32 (raw b32 loads, no cvt in hot path).
// Block: 256 thr = 8 warps (4m x 2n). Block tile 128 x (NF*16). K chunk 32.
// Dual-A (A1/B1 over K1 then A2/B2 over K2) into same accumulators.
// EPI: 0 raw; 1 round_tf(relu(acc+bias)); 2 acc+bias;
//      3 out = outPrev + 0.2*tanh(acc+bias) -> C & ePtr (exact), tfPtr (rounded)
// ---------------------------------------------------------------------------
template<int EPI, int NF>
__global__ __launch_bounds__(256) void tf32_gemm(
    const float* __restrict__ A1, int lda1, int K1,
    const float* __restrict__ A2, int lda2, int K2,
    const float* __restrict__ B1, int ldb1,
    const float* __restrict__ B2, int ldb2,
    const float* __restrict__ bias,
    float* __restrict__ C, int ldc,
    const float* __restrict__ outPrev, float* __restrict__ ePtr,
    float* __restrict__ tfPtr)
{
    constexpr int BROWS = NF * 16;
    constexpr int AW    = 128 * LDS;            // A tile words
    constexpr int TILEW = (128 + BROWS) * LDS;  // words per buffer
    extern __shared__ uint32_t sm[];
    const uint32_t smBase = smem_u32(sm);

    const int tid = threadIdx.x;
    const int wid = tid >> 5, lane = tid & 31;
    const int grp = lane >> 2, tig = lane & 3;
    const int wm  = (wid >> 1) * 32;
    const int wn  = (wid & 1) * (NF * 8);
    const int bm  = blockIdx.y * 128;
    const int bn  = blockIdx.x * BROWS;

    float acc[2][NF][4];
#pragma unroll
    for (int mi = 0; mi < 2; mi++)
#pragma unroll
        for (int ni = 0; ni < NF; ni++)
#pragma unroll
            for (int j = 0; j < 4; j++) acc[mi][ni][j] = 0.0f;

    const int nch1 = K1 >> 5;
    const int nch  = nch1 + (K2 >> 5);

    auto chunkSrc = [&](int c, const float*& Ap, const float*& Bp,
                        int& la, int& lb, int& k0) {
        if (c < nch1) { Ap = A1; Bp = B1; la = lda1; lb = ldb1; k0 = c << 5; }
        else          { Ap = A2; Bp = B2; la = lda2; lb = ldb2; k0 = (c - nch1) << 5; }
    };

    // ldmatrix per-lane address components
    // A x4: lanes 0-7 rows r0..r0+7 @k, 8-15 rows +8 @k, 16-23 rows @k+4, 24-31 rows+8 @k+4
    const int a_r = (lane & 7) + ((lane >> 3) & 1) * 8;
    const int a_c = ((lane >> 4) & 1) * 4;
    // B x4 (covers ni pair 2j,2j+1): lanes 0-7 nrows(2j) @k, 8-15 nrows(2j) @k+4,
    //                                16-23 nrows(2j+1) @k, 24-31 nrows(2j+1) @k+4
    const int b_r = ((lane >> 4) & 1) * 8 + (lane & 7);
    const int b_c = ((lane >> 3) & 1) * 4;
    const uint32_t aOfs0 = (uint32_t)((wm + a_r) * LDS + a_c) * 4u;
    const uint32_t aOfs1 = aOfs0 + 16u * LDS * 4u;
    const uint32_t bOfs  = (uint32_t)(AW + (wn + b_r) * LDS + b_c) * 4u;

    // prologue: prefetch chunk 0
    {
        const float *Ap, *Bp; int la, lb, k0;
        chunkSrc(0, Ap, Bp, la, lb, k0);
        issue_tile<128>(Ap, bm, la, k0, smBase, tid);
        issue_tile<BROWS>(Bp, bn, lb, k0, smBase + AW * 4, tid);
        asm volatile("cp.async.commit_group;" ::: "memory");
    }

#pragma unroll 1
    for (int c = 0; c < nch; ++c) {
        const uint32_t pb = smBase + (uint32_t)(c & 1) * TILEW * 4u;
        if (c + 1 < nch) {
            const float *Ap, *Bp; int la, lb, k0;
            chunkSrc(c + 1, Ap, Bp, la, lb, k0);
            const uint32_t nb = smBase + (uint32_t)((c + 1) & 1) * TILEW * 4u;
            issue_tile<128>(Ap, bm, la, k0, nb, tid);
            issue_tile<BROWS>(Bp, bn, lb, k0, nb + AW * 4, tid);
            asm volatile("cp.async.commit_group;" ::: "memory");
            asm volatile("cp.async.wait_group 1;" ::: "memory");
        } else {
            asm volatile("cp.async.wait_group 0;" ::: "memory");
        }
        __syncthreads();
#pragma unroll
        for (int s = 0; s < 4; s++) {
            uint32_t a[2][4], bf[NF][2];
            ldm4(a[0], pb + aOfs0 + s * 32);
            ldm4(a[1], pb + aOfs1 + s * 32);
#pragma unroll
            for (int j = 0; j < NF / 2; j++) {
                uint32_t t[4];
                ldm4(t, pb + bOfs + (uint32_t)j * (16u * LDS * 4u) + s * 32);
                bf[2*j][0]   = t[0]; bf[2*j][1]   = t[1];
                bf[2*j+1][0] = t[2]; bf[2*j+1][1] = t[3];
            }
#pragma unroll
            for (int mi = 0; mi < 2; mi++)
#pragma unroll
                for (int ni = 0; ni < NF; ni++)
                    mma_tf32(acc[mi][ni], a[mi][0], a[mi][1], a[mi][2], a[mi][3],
                             bf[ni][0], bf[ni][1]);
        }
        __syncthreads();
    }

    // Epilogue. C frag: c0,c1 at (grp, 2*tig..+1); c2,c3 at (grp+8, same cols).
    auto emit = [&](int row, int col, float v0, float v1) {
        if (EPI == 0) {
            *(float2*)&C[(size_t)row * ldc + col] = make_float2(v0, v1);
        } else if (EPI == 1) {
            v0 = rtf(fmaxf(v0 + bias[col], 0.f));
            v1 = rtf(fmaxf(v1 + bias[col + 1], 0.f));
            *(float2*)&C[(size_t)row * ldc + col] = make_float2(v0, v1);
        } else if (EPI == 2) {
            *(float2*)&C[(size_t)row * ldc + col] =
                make_float2(v0 + bias[col], v1 + bias[col + 1]);
        } else {
            float2 op = *(const float2*)&outPrev[(size_t)row * OUT_STRIDE + col];
            float2 o;
            o.x = op.x + 0.2f * tanhf(v0 + bias[col]);
            o.y = op.y + 0.2f * tanhf(v1 + bias[col + 1]);
            *(float2*)&C[(size_t)row * ldc + col] = o;             // out (exact)
            if (ePtr) *(float2*)&ePtr[(size_t)row * E_STRIDE + col] = o;  // e (exact)
            *(float2*)&tfPtr[(size_t)row * ZD + col] = make_float2(rtf(o.x), rtf(o.y));
        }
    };

#pragma unroll
    for (int mi = 0; mi < 2; mi++) {
        const int r0 = bm + wm + mi * 16 + grp;
#pragma unroll
        for (int ni = 0; ni < NF; ni++) {
            const int col = bn + wn + ni * 8 + 2 * tig;
            emit(r0,     col, acc[mi][ni][0], acc[mi][ni][1]);
            emit(r0 + 8, col, acc[mi][ni][2], acc[mi][ni][3]);
        }
    }
}

// ---------------------------------------------------------------------------
// LSTM pointwise: h stored tf32-rounded (GEMM operand); c exact (recurrence);
// hc row stored rounded (fc1 operand) — numerically identical to round-at-load.
// ---------------------------------------------------------------------------
__global__ void lstm_pointwise(
    const float* __restrict__ gates,
    const float* __restrict__ bih, const float* __restrict__ bhh,
    float* __restrict__ h, float* __restrict__ c,
    int useC,
    float* __restrict__ hcRow, int hcStride)
{
    int idx = blockIdx.x * blockDim.x + threadIdx.x;
    if (idx >= BN * HD) return;
    int b = idx / HD, j = idx - b * HD;
    const float* g = gates + (size_t)b * G4;
    float gi = g[j        ] + bih[j        ] + bhh[j        ];
    float gf = g[j +   HD ] + bih[j +   HD ] + bhh[j +   HD ];
    float gg = g[j + 2*HD ] + bih[j + 2*HD ] + bhh[j + 2*HD ];
    float go = g[j + 3*HD ] + bih[j + 3*HD ] + bhh[j + 3*HD ];
    float cn = sigf(gi) * tanhf(gg);
    if (useC) cn += sigf(gf) * c[idx];
    float hn = sigf(go) * tanhf(cn);
    c[idx] = cn;
    h[idx] = rtf(hn);
    if (hcRow) {
        float* r = hcRow + (size_t)b * hcStride;
        r[j] = rtf(hn);
        r[HD + j] = rtf(cn);
    }
}

// out row 0 = z (exact), e row 0 = z (exact), outTf = round(z)
__global__ void init_out(const float* __restrict__ z,
                         float* __restrict__ out, float* __restrict__ e,
                         float* __restrict__ outTf)
{
    int idx = blockIdx.x * blockDim.x + threadIdx.x;
    if (idx >= BN * ZD) return;
    int b = idx >> 9, n = idx & 511;
    float v = z[idx];
    out[(size_t)b * OUT_STRIDE + n] = v;
    e[(size_t)b * E_STRIDE + n] = v;
    outTf[idx] = rtf(v);
}

// dst[i] = round_tf32(src[i])
__global__ void round_copy(const float* __restrict__ src, float* __restrict__ dst, int n)
{
    int idx = blockIdx.x * blockDim.x + threadIdx.x;
    if (idx < n) dst[idx] = rtf(src[idx]);
}

// wT[n, k] = round(w[k, n])   (w: [H=384, Z=512] -> wT: [512, 384] K-major)
__global__ void transpose_round_w(const float* __restrict__ w, float* __restrict__ wT)
{
    int idx = blockIdx.x * blockDim.x + threadIdx.x;
    if (idx >= ZD * HD) return;
    int n = idx / HD, k = idx - n * HD;
    wT[idx] = rtf(w[(size_t)k * ZD + n]);
}

extern "C" void kernel_launch(void* const* d_in, const int* in_sizes, int n_in,
                              void* d_out, int out_size)
{
    (void)in_sizes; (void)n_in; (void)out_size;
    const float* z       = (const float*)d_in[0];
    const float* Wih_enc = (const float*)d_in[1];
    const float* Whh_enc = (const float*)d_in[2];
    const float* bih_enc = (const float*)d_in[3];
    const float* bhh_enc = (const float*)d_in[4];
    const float* Wih     = (const float*)d_in[5];
    const float* Whh     = (const float*)d_in[6];
    const float* bih     = (const float*)d_in[7];
    const float* bhh     = (const float*)d_in[8];
    const float* w       = (const float*)d_in[9];
    const float* b       = (const float*)d_in[10];
    const float* fc1_w   = (const float*)d_in[11];
    const float* fc1_b   = (const float*)d_in[12];
    const float* fc2_w   = (const float*)d_in[13];
    const float* fc2_b   = (const float*)d_in[14];
    (void)Whh_enc; // h0 = 0 so the enc Whh term vanishes

    float* out  = (float*)d_out;
    float* e    = out + (size_t)BN * TN * ZD;
    float* erec = e + (size_t)SEQ * ZD;

    float *gates, *h, *c, *hc, *mid, *outTf;
    float *WihEnc_t, *Wih_t, *Whh_t, *fc1_t, *fc2_t, *wT;
    cudaGetSymbolAddress((void**)&gates,    g_gates);
    cudaGetSymbolAddress((void**)&h,        g_h);
    cudaGetSymbolAddress((void**)&c,        g_c);
    cudaGetSymbolAddress((void**)&hc,       g_hc);
    cudaGetSymbolAddress((void**)&mid,      g_mid);
    cudaGetSymbolAddress((void**)&outTf,    g_outTf);
    cudaGetSymbolAddress((void**)&WihEnc_t, g_WihEnc_t);
    cudaGetSymbolAddress((void**)&Wih_t,    g_Wih_t);
    cudaGetSymbolAddress((void**)&Whh_t,    g_Whh_t);
    cudaGetSymbolAddress((void**)&fc1_t,    g_fc1_t);
    cudaGetSymbolAddress((void**)&fc2_t,    g_fc2_t);
    cudaGetSymbolAddress((void**)&wT,       g_wT);

    constexpr int SMEM8 = 2 * (128 + 128) * LDS * 4;  // 73728
    constexpr int SMEM4 = 2 * (128 + 64)  * LDS * 4;  // 55296
    cudaFuncSetAttribute(tf32_gemm<0,8>, cudaFuncAttributeMaxDynamicSharedMemorySize, SMEM8);
    cudaFuncSetAttribute(tf32_gemm<1,8>, cudaFuncAttributeMaxDynamicSharedMemorySize, SMEM8);
    cudaFuncSetAttribute(tf32_gemm<2,8>, cudaFuncAttributeMaxDynamicSharedMemorySize, SMEM8);
    cudaFuncSetAttribute(tf32_gemm<3,4>, cudaFuncAttributeMaxDynamicSharedMemorySize, SMEM4);

    const dim3 blk(256);

    // One-time weight rounding + out init (cheap)
    init_out<<<(BN * ZD) / 256, 256>>>(z, out, e, outTf);
    round_copy<<<(G4 * ZD) / 256, 256>>>(Wih_enc, WihEnc_t, G4 * ZD);
    round_copy<<<(G4 * ZD) / 256, 256>>>(Wih, Wih_t, G4 * ZD);
    round_copy<<<(G4 * HD) / 256, 256>>>(Whh, Whh_t, G4 * HD);
    round_copy<<<(ZD * HC_STRIDE) / 256, 256>>>(fc1_w, fc1_t, ZD * HC_STRIDE);
    round_copy<<<(ZD * ZD) / 256, 256>>>(fc2_w, fc2_t, ZD * ZD);
    transpose_round_w<<<(ZD * HD) / 256, 256>>>(w, wT);

    // Encoder: gates = round(z) @ WihEnc_t^T   (h0 = c0 = 0)
    tf32_gemm<0, 8><<<dim3(G4 / 128, BN / 128), blk, SMEM8>>>(
        outTf, ZD, ZD, nullptr, 0, 0, WihEnc_t, ZD, nullptr, 0,
        nullptr, gates, G4, nullptr, nullptr, nullptr);
    lstm_pointwise<<<(BN * HD) / 256, 256>>>(
        gates, bih_enc, bhh_enc, h, c, 0, nullptr, 0);

    // 31 recurrent steps
    for (int k = 0; k < TN - 1; ++k) {
        // gates = outTf @ Wih_t^T + h @ Whh_t^T
        tf32_gemm<0, 8><<<dim3(G4 / 128, BN / 128), blk, SMEM8>>>(
            outTf, ZD, ZD,
            h, HD, HD,
            Wih_t, ZD, Whh_t, HD,
            nullptr, gates, G4, nullptr, nullptr, nullptr);
        lstm_pointwise<<<(BN * HD) / 256, 256>>>(
            gates, bih, bhh, h, c, 1,
            hc + (size_t)k * HC_STRIDE, (TN - 1) * HC_STRIDE);
        // out_{k+1} = out_k + 0.2*tanh(h2 @ wT^T + b); e row k+1; outTf = round(out_{k+1})
        tf32_gemm<3, 4><<<dim3(ZD / 64, BN / 128), blk, SMEM4>>>(
            h, HD, HD, nullptr, 0, 0, wT, HD, nullptr, 0,
            b, out + (size_t)(k + 1) * ZD, OUT_STRIDE,
            out + (size_t)k * ZD,
            (k + 1 <= TN - 2) ? (e + (size_t)(k + 1) * ZD) : nullptr,
            outTf);
    }

    // e_rec = relu(hc @ fc1_t^T + fc1_b) @ fc2_t^T + fc2_b
    tf32_gemm<1, 8><<<dim3(ZD / 128, SEQ / 128), blk, SMEM8>>>(
        hc, HC_STRIDE, HC_STRIDE, nullptr, 0, 0, fc1_t, HC_STRIDE, nullptr, 0,
        fc1_b, mid, ZD, nullptr, nullptr, nullptr);
    tf32_gemm<2, 8><<<dim3(ZD / 128, SEQ / 128), blk, SMEM8>>>(
        mid, ZD, ZD, nullptr, 0, 0, fc2_t, ZD, nullptr, 0,
        fc2_b, erec, ZD, nullptr, nullptr, nullptr);
}

// round 11
// speedup vs baseline: 3.6787x; 1.2153x over previous
#include <cuda_runtime.h>
#include <math.h>
#include <stdint.h>

// Problem constants (fixed shapes)
#define BN 2048
#define ZD 512
#define HD 384
#define TN 32
#define G4 (4*HD)              // 1536
#define OUT_STRIDE (TN*ZD)     // 16384
#define E_STRIDE ((TN-1)*ZD)   // 15872
#define HC_STRIDE (2*HD)       // 768
#define SEQ ((TN-1)*BN)        // 63488

#define LDS 36                 // smem row stride in words (32 + 4 pad)

// Scratch (allocation-free: __device__ globals)
__device__ float g_h0[(size_t)BN*HD];      // tf32-rounded h (ping)
__device__ float g_h1[(size_t)BN*HD];      // tf32-rounded h (pong)
__device__ float g_c[(size_t)BN*HD];       // exact c
__device__ float g_hc[(size_t)SEQ*HC_STRIDE];   // tf32-rounded (h,c)
__device__ float g_mid[(size_t)SEQ*ZD];         // tf32-rounded fc1 output
__device__ float g_outTf[(size_t)BN*ZD];        // tf32-rounded out row (current step)
// tf32-rounded, gate-interleave-PERMUTED weights (row P <- row g*HD+j)
__device__ float g_WihEnc_t[(size_t)G4*ZD];
__device__ float g_Wih_t[(size_t)G4*ZD];
__device__ float g_Whh_t[(size_t)G4*HD];
__device__ float g_bsumEnc[G4];                 // permuted bih_enc+bhh_enc
__device__ float g_bsum[G4];                    // permuted bih+bhh
__device__ float g_fc1_t[(size_t)ZD*HC_STRIDE];
__device__ float g_fc2_t[(size_t)ZD*ZD];
__device__ float g_wT[(size_t)ZD*HD];           // rounded transpose of w

__device__ __forceinline__ float sigf(float x) { return 1.0f / (1.0f + __expf(-x)); }

__device__ __forceinline__ uint32_t f2tf(float x) {
    uint32_t r;
    asm("cvt.rna.tf32.f32 %0, %1;" : "=r"(r) : "f"(x));
    return r;
}
__device__ __forceinline__ float rtf(float x) { return __uint_as_float(f2tf(x)); }

__device__ __forceinline__ uint32_t smem_u32(const void* p) {
    uint32_t a;
    asm("{ .reg .u64 t; cvta.to.shared.u64 t, %1; cvt.u32.u64 %0, t; }" : "=r"(a) : "l"(p));
    return a;
}

__device__ __forceinline__ void mma_tf32(
    float* c, uint32_t a0, uint32_t a1, uint32_t a2, uint32_t a3,
    uint32_t b0, uint32_t b1)
{
    asm volatile(
        "mma.sync.aligned.m16n8k8.row.col.f32.tf32.tf32.f32 "
        "{%0,%1,%2,%3}, {%4,%5,%6,%7}, {%8,%9}, {%0,%1,%2,%3};"
        : "+f"(c[0]), "+f"(c[1]), "+f"(c[2]), "+f"(c[3])
        : "r"(a0), "r"(a1), "r"(a2), "r"(a3), "r"(b0), "r"(b1));
}

__device__ __forceinline__ void ldm4(uint32_t* r, uint32_t addr) {
    asm volatile("ldmatrix.sync.aligned.m8n8.x4.shared.b16 {%0,%1,%2,%3}, [%4];"
        : "=r"(r[0]), "=r"(r[1]), "=r"(r[2]), "=r"(r[3]) : "r"(addr));
}

__device__ __forceinline__ void cpa16(uint32_t dst, const void* src) {
    asm volatile("cp.async.ca.shared.global [%0], [%1], 16;" :: "r"(dst), "l"(src));
}

// Issue cp.async for a [ROWS x 32 floats] K-major tile (row stride LDS words).
// Generic: ROWS*8 16B segments, 256 threads, coalesced (8 thr/row).
template<int ROWS>
__device__ __forceinline__ void issue_tile(
    const float* __restrict__ G, int row0, int ld, int k0, uint32_t smemBase, int tid)
{
#pragma unroll
    for (int s = tid; s < ROWS * 8; s += 256) {
        const int row = s >> 3, c4 = s & 7;
        cpa16(smemBase + (uint32_t)(row * LDS + c4 * 4) * 4u,
              G + (size_t)(row0 + row) * ld + k0 + c4 * 4);
    }
}

// ---------------------------------------------------------------------------
// tf32 mma.sync GEMM, NT, cp.async double-buffered, ldmatrix fragments.
// All inputs PRE-ROUNDED to tf32. Block: 256 thr = 8 warps (4m x 2n).
// Block tile 128 x (NF*16). K chunk 32. Dual-A into same accumulators.
// EPI: 1 round_tf(relu(acc+bias)) -> C
//      2 acc+bias -> C
//      3 out = outPrev + 0.2*tanh(acc+bias) -> C & ePtr (exact), tfPtr (rounded)
//      4 fused LSTM cell (NF=12, gate-interleaved weights):
//           bias = permuted (bih+bhh); writes hOut (rounded), c, hcRow
// ---------------------------------------------------------------------------
template<int EPI, int NF>
__global__ __launch_bounds__(256) void tf32_gemm(
    const float* __restrict__ A1, int lda1, int K1,
    const float* __restrict__ A2, int lda2, int K2,
    const float* __restrict__ B1, int ldb1,
    const float* __restrict__ B2, int ldb2,
    const float* __restrict__ bias,
    float* __restrict__ C, int ldc,
    const float* __restrict__ outPrev, float* __restrict__ ePtr,
    float* __restrict__ tfPtr,
    float* __restrict__ hOut, float* __restrict__ cPtr,
    int useC, float* __restrict__ hcRow, int hcStride)
{
    constexpr int BROWS = NF * 16;
    constexpr int AW    = 128 * LDS;
    constexpr int TILEW = (128 + BROWS) * LDS;
    extern __shared__ uint32_t sm[];
    const uint32_t smBase = smem_u32(sm);

    const int tid = threadIdx.x;
    const int wid = tid >> 5, lane = tid & 31;
    const int grp = lane >> 2, tig = lane & 3;
    const int wm  = (wid >> 1) * 32;
    const int wn  = (wid & 1) * (NF * 8);
    const int bm  = blockIdx.y * 128;
    const int bn  = blockIdx.x * BROWS;

    float acc[2][NF][4];
#pragma unroll
    for (int mi = 0; mi < 2; mi++)
#pragma unroll
        for (int ni = 0; ni < NF; ni++)
#pragma unroll
            for (int j = 0; j < 4; j++) acc[mi][ni][j] = 0.0f;

    const int nch1 = K1 >> 5;
    const int nch  = nch1 + (K2 >> 5);

    auto chunkSrc = [&](int c, const float*& Ap, const float*& Bp,
                        int& la, int& lb, int& k0) {
        if (c < nch1) { Ap = A1; Bp = B1; la = lda1; lb = ldb1; k0 = c << 5; }
        else          { Ap = A2; Bp = B2; la = lda2; lb = ldb2; k0 = (c - nch1) << 5; }
    };

    const int a_r = (lane & 7) + ((lane >> 3) & 1) * 8;
    const int a_c = ((lane >> 4) & 1) * 4;
    const int b_r = ((lane >> 4) & 1) * 8 + (lane & 7);
    const int b_c = ((lane >> 3) & 1) * 4;
    const uint32_t aOfs0 = (uint32_t)((wm + a_r) * LDS + a_c) * 4u;
    const uint32_t aOfs1 = aOfs0 + 16u * LDS * 4u;
    const uint32_t bOfs  = (uint32_t)(AW + (wn + b_r) * LDS + b_c) * 4u;

    {
        const float *Ap, *Bp; int la, lb, k0;
        chunkSrc(0, Ap, Bp, la, lb, k0);
        issue_tile<128>(Ap, bm, la, k0, smBase, tid);
        issue_tile<BROWS>(Bp, bn, lb, k0, smBase + AW * 4, tid);
        asm volatile("cp.async.commit_group;" ::: "memory");
    }

#pragma unroll 1
    for (int c = 0; c < nch; ++c) {
        const uint32_t pb = smBase + (uint32_t)(c & 1) * TILEW * 4u;
        if (c + 1 < nch) {
            const float *Ap, *Bp; int la, lb, k0;
            chunkSrc(c + 1, Ap, Bp, la, lb, k0);
            const uint32_t nb = smBase + (uint32_t)((c + 1) & 1) * TILEW * 4u;
            issue_tile<128>(Ap, bm, la, k0, nb, tid);
            issue_tile<BROWS>(Bp, bn, lb, k0, nb + AW * 4, tid);
            asm volatile("cp.async.commit_group;" ::: "memory");
            asm volatile("cp.async.wait_group 1;" ::: "memory");
        } else {
            asm volatile("cp.async.wait_group 0;" ::: "memory");
        }
        __syncthreads();
#pragma unroll
        for (int s = 0; s < 4; s++) {
            uint32_t a[2][4], bf[NF][2];
            ldm4(a[0], pb + aOfs0 + s * 32);
            ldm4(a[1], pb + aOfs1 + s * 32);
#pragma unroll
            for (int j = 0; j < NF / 2; j++) {
                uint32_t t[4];
                ldm4(t, pb + bOfs + (uint32_t)j * (16u * LDS * 4u) + s * 32);
                bf[2*j][0]   = t[0]; bf[2*j][1]   = t[1];
                bf[2*j+1][0] = t[2]; bf[2*j+1][1] = t[3];
            }
#pragma unroll
            for (int mi = 0; mi < 2; mi++)
#pragma unroll
                for (int ni = 0; ni < NF; ni++)
                    mma_tf32(acc[mi][ni], a[mi][0], a[mi][1], a[mi][2], a[mi][3],
                             bf[ni][0], bf[ni][1]);
        }
        __syncthreads();
    }

    if (EPI == 4) {
        // Fused LSTM cell epilogue (NF must be 12: warp tile = 96 cols = 24 units).
        // Permutation: col P = 96*Wg + 8*(4v+g) + 2t + b  <->  unit j = 24*Wg+6t+3b+v.
        const int Wg = blockIdx.x * 2 + (wid & 1);
        const int jbase = 24 * Wg + 6 * tig;
        float bs[2][3][4];
        const float* bp = bias + 96 * Wg + 2 * tig;
#pragma unroll
        for (int b2 = 0; b2 < 2; b2++)
#pragma unroll
            for (int v = 0; v < 3; v++)
#pragma unroll
                for (int g = 0; g < 4; g++)
                    bs[b2][v][g] = bp[8 * (4 * v + g) + b2];
#pragma unroll
        for (int mi = 0; mi < 2; mi++) {
#pragma unroll
            for (int rr = 0; rr < 2; rr++) {
                const int R = bm + wm + mi * 16 + grp + rr * 8;
#pragma unroll
                for (int b2 = 0; b2 < 2; b2++) {
#pragma unroll
                    for (int v = 0; v < 3; v++) {
                        const float gi = acc[mi][4*v+0][rr*2+b2] + bs[b2][v][0];
                        const float gf = acc[mi][4*v+1][rr*2+b2] + bs[b2][v][1];
                        const float gg = acc[mi][4*v+2][rr*2+b2] + bs[b2][v][2];
                        const float go = acc[mi][4*v+3][rr*2+b2] + bs[b2][v][3];
                        const int j = jbase + 3 * b2 + v;
                        float cn = sigf(gi) * tanhf(gg);
                        if (useC) cn += sigf(gf) * cPtr[(size_t)R * HD + j];
                        const float hn = sigf(go) * tanhf(cn);
                        cPtr[(size_t)R * HD + j] = cn;
                        hOut[(size_t)R * HD + j] = rtf(hn);
                        if (hcRow) {
                            hcRow[(size_t)R * hcStride + j]      = rtf(hn);
                            hcRow[(size_t)R * hcStride + HD + j] = rtf(cn);
                        }
                    }
                }
            }
        }
        return;
    }

    // Epilogues 1-3. C frag: c0,c1 at (grp, 2*tig..+1); c2,c3 at (grp+8, same).
    auto emit = [&](int row, int col, float v0, float v1) {
        if (EPI == 1) {
            v0 = rtf(fmaxf(v0 + bias[col], 0.f));
            v1 = rtf(fmaxf(v1 + bias[col + 1], 0.f));
            *(float2*)&C[(size_t)row * ldc + col] = make_float2(v0, v1);
        } else if (EPI == 2) {
            *(float2*)&C[(size_t)row * ldc + col] =
                make_float2(v0 + bias[col], v1 + bias[col + 1]);
        } else {
            float2 op = *(const float2*)&outPrev[(size_t)row * OUT_STRIDE + col];
            float2 o;
            o.x = op.x + 0.2f * tanhf(v0 + bias[col]);
            o.y = op.y + 0.2f * tanhf(v1 + bias[col + 1]);
            *(float2*)&C[(size_t)row * ldc + col] = o;
            if (ePtr) *(float2*)&ePtr[(size_t)row * E_STRIDE + col] = o;
            *(float2*)&tfPtr[(size_t)row * ZD + col] = make_float2(rtf(o.x), rtf(o.y));
        }
    };

#pragma unroll
    for (int mi = 0; mi < 2; mi++) {
        const int r0 = bm + wm + mi * 16 + grp;
#pragma unroll
        for (int ni = 0; ni < NF; ni++) {
            const int col = bn + wn + ni * 8 + 2 * tig;
            emit(r0,     col, acc[mi][ni][0], acc[mi][ni][1]);
            emit(r0 + 8, col, acc[mi][ni][2], acc[mi][ni][3]);
        }
    }
}

// ---------------------------------------------------------------------------
// Setup kernels
// ---------------------------------------------------------------------------
// out row 0 = z (exact), e row 0 = z (exact), outTf = round(z)
__global__ void init_out(const float* __restrict__ z,
                         float* __restrict__ out, float* __restrict__ e,
                         float* __restrict__ outTf)
{
    int idx = blockIdx.x * blockDim.x + threadIdx.x;
    if (idx >= BN * ZD) return;
    int b = idx >> 9, n = idx & 511;
    float v = z[idx];
    out[(size_t)b * OUT_STRIDE + n] = v;
    e[(size_t)b * E_STRIDE + n] = v;
    outTf[idx] = rtf(v);
}

__global__ void round_copy(const float* __restrict__ src, float* __restrict__ dst, int n)
{
    int idx = blockIdx.x * blockDim.x + threadIdx.x;
    if (idx < n) dst[idx] = rtf(src[idx]);
}

// Gate-interleave permutation of weight rows (+ tf32 rounding).
// dst row P <- src row g*HD + j, where P = 96W + 8(4v+g) + 2t + b, j = 24W+6t+3b+v.
__global__ void perm_weight(const float* __restrict__ src, float* __restrict__ dst, int K)
{
    int idx = blockIdx.x * blockDim.x + threadIdx.x;
    if (idx >= G4 * K) return;
    int P = idx / K, k = idx - P * K;
    int W = P / 96, r = P - W * 96;
    int k8 = r >> 3, t = (r >> 1) & 3, b2 = r & 1;
    int v = k8 >> 2, g = k8 & 3;
    int j = 24 * W + 6 * t + 3 * b2 + v;
    dst[idx] = rtf(src[(size_t)(g * HD + j) * K + k]);
}

__global__ void perm_bias(const float* __restrict__ b1, const float* __restrict__ b2,
                          float* __restrict__ dst)
{
    int P = blockIdx.x * blockDim.x + threadIdx.x;
    if (P >= G4) return;
    int W = P / 96, r = P - W * 96;
    int k8 = r >> 3, t = (r >> 1) & 3, bb = r & 1;
    int v = k8 >> 2, g = k8 & 3;
    int j = 24 * W + 6 * t + 3 * bb + v;
    dst[P] = b1[g * HD + j] + b2[g * HD + j];
}

// wT[n, k] = round(w[k, n])   (w: [H=384, Z=512] -> wT: [512, 384] K-major)
__global__ void transpose_round_w(const float* __restrict__ w, float* __restrict__ wT)
{
    int idx = blockIdx.x * blockDim.x + threadIdx.x;
    if (idx >= ZD * HD) return;
    int n = idx / HD, k = idx - n * HD;
    wT[idx] = rtf(w[(size_t)k * ZD + n]);
}

extern "C" void kernel_launch(void* const* d_in, const int* in_sizes, int n_in,
                              void* d_out, int out_size)
{
    (void)in_sizes; (void)n_in; (void)out_size;
    const float* z       = (const float*)d_in[0];
    const float* Wih_enc = (const float*)d_in[1];
    const float* bih_enc = (const float*)d_in[3];
    const float* bhh_enc = (const float*)d_in[4];
    const float* Wih     = (const float*)d_in[5];
    const float* Whh     = (const float*)d_in[6];
    const float* bih     = (const float*)d_in[7];
    const float* bhh     = (const float*)d_in[8];
    const float* w       = (const float*)d_in[9];
    const float* b       = (const float*)d_in[10];
    const float* fc1_w   = (const float*)d_in[11];
    const float* fc1_b   = (const float*)d_in[12];
    const float* fc2_w   = (const float*)d_in[13];
    const float* fc2_b   = (const float*)d_in[14];
    // d_in[2] (Whh_enc) unused: h0 = 0 so the enc Whh term vanishes

    float* out  = (float*)d_out;
    float* e    = out + (size_t)BN * TN * ZD;
    float* erec = e + (size_t)SEQ * ZD;

    float *h0, *h1, *c, *hc, *mid, *outTf;
    float *WihEnc_t, *Wih_t, *Whh_t, *bsumEnc, *bsum, *fc1_t, *fc2_t, *wT;
    cudaGetSymbolAddress((void**)&h0,       g_h0);
    cudaGetSymbolAddress((void**)&h1,       g_h1);
    cudaGetSymbolAddress((void**)&c,        g_c);
    cudaGetSymbolAddress((void**)&hc,       g_hc);
    cudaGetSymbolAddress((void**)&mid,      g_mid);
    cudaGetSymbolAddress((void**)&outTf,    g_outTf);
    cudaGetSymbolAddress((void**)&WihEnc_t, g_WihEnc_t);
    cudaGetSymbolAddress((void**)&Wih_t,    g_Wih_t);
    cudaGetSymbolAddress((void**)&Whh_t,    g_Whh_t);
    cudaGetSymbolAddress((void**)&bsumEnc,  g_bsumEnc);
    cudaGetSymbolAddress((void**)&bsum,     g_bsum);
    cudaGetSymbolAddress((void**)&fc1_t,    g_fc1_t);
    cudaGetSymbolAddress((void**)&fc2_t,    g_fc2_t);
    cudaGetSymbolAddress((void**)&wT,       g_wT);

    float* hbuf[2] = { h0, h1 };

    constexpr int SMEM12 = 2 * (128 + 192) * LDS * 4;  // 92160
    constexpr int SMEM8  = 2 * (128 + 128) * LDS * 4;  // 73728
    constexpr int SMEM4  = 2 * (128 + 64)  * LDS * 4;  // 55296
    cudaFuncSetAttribute(tf32_gemm<4,12>, cudaFuncAttributeMaxDynamicSharedMemorySize, SMEM12);
    cudaFuncSetAttribute(tf32_gemm<1,8>,  cudaFuncAttributeMaxDynamicSharedMemorySize, SMEM8);
    cudaFuncSetAttribute(tf32_gemm<2,8>,  cudaFuncAttributeMaxDynamicSharedMemorySize, SMEM8);
    cudaFuncSetAttribute(tf32_gemm<3,4>,  cudaFuncAttributeMaxDynamicSharedMemorySize, SMEM4);

    const dim3 blk(256);

    // One-time setup (cheap)
    init_out<<<(BN * ZD) / 256, 256>>>(z, out, e, outTf);
    perm_weight<<<(G4 * ZD) / 256, 256>>>(Wih_enc, WihEnc_t, ZD);
    perm_weight<<<(G4 * ZD) / 256, 256>>>(Wih, Wih_t, ZD);
    perm_weight<<<(G4 * HD) / 256, 256>>>(Whh, Whh_t, HD);
    perm_bias<<<G4 / 256, 256>>>(bih_enc, bhh_enc, bsumEnc);
    perm_bias<<<G4 / 256, 256>>>(bih, bhh, bsum);
    round_copy<<<(ZD * HC_STRIDE) / 256, 256>>>(fc1_w, fc1_t, ZD * HC_STRIDE);
    round_copy<<<(ZD * ZD) / 256, 256>>>(fc2_w, fc2_t, ZD * ZD);
    transpose_round_w<<<(ZD * HD) / 256, 256>>>(w, wT);

    // Encoder: fused GEMM + LSTM cell (h0 = c0 = 0 -> useC=0), writes hbuf[0], c
    tf32_gemm<4, 12><<<dim3(G4 / 192, BN / 128), blk, SMEM12>>>(
        outTf, ZD, ZD, nullptr, 0, 0, WihEnc_t, ZD, nullptr, 0,
        bsumEnc, nullptr, 0, nullptr, nullptr, nullptr,
        hbuf[0], c, 0, nullptr, 0);

    // 31 recurrent steps: 2 kernels each
    for (int k = 0; k < TN - 1; ++k) {
        float* hIn  = hbuf[k & 1];
        float* hNew = hbuf[(k + 1) & 1];
        // fused: gates = outTf @ Wih_t^T + hIn @ Whh_t^T; cell -> hNew, c, hc row k
        tf32_gemm<4, 12><<<dim3(G4 / 192, BN / 128), blk, SMEM12>>>(
            outTf, ZD, ZD,
            hIn, HD, HD,
            Wih_t, ZD, Whh_t, HD,
            bsum, nullptr, 0, nullptr, nullptr, nullptr,
            hNew, c, 1, hc + (size_t)k * HC_STRIDE, (TN - 1) * HC_STRIDE);
        // out_{k+1} = out_k + 0.2*tanh(hNew @ wT^T + b); e row k+1; outTf refresh
        tf32_gemm<3, 4><<<dim3(ZD / 64, BN / 128), blk, SMEM4>>>(
            hNew, HD, HD, nullptr, 0, 0, wT, HD, nullptr, 0,
            b, out + (size_t)(k + 1) * ZD, OUT_STRIDE,
            out + (size_t)k * ZD,
            (k + 1 <= TN - 2) ? (e + (size_t)(k + 1) * ZD) : nullptr,
            outTf, nullptr, nullptr, 0, nullptr, 0);
    }

    // e_rec = relu(hc @ fc1_t^T + fc1_b) @ fc2_t^T + fc2_b
    tf32_gemm<1, 8><<<dim3(ZD / 128, SEQ / 128), blk, SMEM8>>>(
        hc, HC_STRIDE, HC_STRIDE, nullptr, 0, 0, fc1_t, HC_STRIDE, nullptr, 0,
        fc1_b, mid, ZD, nullptr, nullptr, nullptr, nullptr, nullptr, 0, nullptr, 0);
    tf32_gemm<2, 8><<<dim3(ZD / 128, SEQ / 128), blk, SMEM8>>>(
        mid, ZD, ZD, nullptr, 0, 0, fc2_t, ZD, nullptr, 0,
        fc2_b, erec, ZD, nullptr, nullptr, nullptr, nullptr, nullptr, 0, nullptr, 0);
}